// round 1
// baseline (speedup 1.0000x reference)
#include <cuda_runtime.h>
#include <cuda_bf16.h>

// Problem constants (fixed by the reference)
#define BATCH 16
#define MCTRL 64
#define NCTRL 64
#define DEG   3
#define LKNOT 68          // M + P + 1
#define NSPAN (LKNOT - 2*DEG)   // 62 candidate spans
#define OUTU  256
#define OUTV  256

// Scratch (allocation-free rule: __device__ globals)
// Nu == Nv and uspan == vspan because the reference builds V from knot_u and
// u/v linspaces + degrees are identical. One table serves both directions.
__device__ float4 g_basis[BATCH][OUTU];
__device__ int    g_span [BATCH][OUTU];

// ---------------------------------------------------------------------------
// Kernel 1: normalized knots (cumsum), span search, Cox-de Boor deg-3 basis.
// One block per batch, one thread per parameter sample.
// ---------------------------------------------------------------------------
__global__ void __launch_bounds__(OUTU) basis_kernel(const float* __restrict__ knot_u) {
    const int b = blockIdx.x;
    __shared__ float K[LKNOT];

    if (threadIdx.x == 0) {
        // Sequential fp32 cumsum (matches jnp.cumsum semantics), then normalize:
        // K[i] = (c[i] - c[0]) / (c[last] - c[0])
        const float* kn = knot_u + b * LKNOT;
        float c = 0.f;
        float cs[LKNOT];
        #pragma unroll 1
        for (int i = 0; i < LKNOT; i++) { c += kn[i]; cs[i] = c; }
        const float c0  = cs[0];
        const float den = cs[LKNOT - 1] - c0;
        #pragma unroll 1
        for (int i = 0; i < LKNOT; i++) K[i] = (cs[i] - c0) / den;
    }
    __syncthreads();

    const int t = threadIdx.x;  // 0..255
    // jnp.linspace(1e-5, 1-1e-5, 256): start + i*step, endpoint exact.
    const float start = 1e-5f;
    const float stop  = 1.0f - 1e-5f;
    const float step  = (stop - start) / (float)(OUTU - 1);
    float tv = start + (float)t * step;
    if (t == OUTU - 1) tv = stop;

    // _find_span: argmin over cand = (d > 1e-8 ? d : 1.0), first-occurrence ties.
    float best = 3.402823466e+38f;
    int   arg  = 0;
    #pragma unroll 1
    for (int s = 0; s < NSPAN; s++) {
        float d    = tv - K[s + DEG];
        float cand = (d > 1e-8f) ? d : 1.0f;
        if (cand < best) { best = cand; arg = s; }
    }
    const int span = arg + DEG;

    // Cox-de Boor recursion, exactly mirroring the reference (incl. the
    // (K1 - t) + (t - K2) denominator form).
    float Nb[DEG + 1];
    Nb[0] = 1.f;
    #pragma unroll
    for (int k = 1; k <= DEG; k++) {
        float saved = 0.f;
        #pragma unroll
        for (int r = 0; r < k; r++) {
            const float K1 = K[span + r + 1];
            const float K2 = K[span + 1 - k + r];
            const float denom = (K1 - tv) + (tv - K2);
            const float temp  = Nb[r] / denom;
            Nb[r] = saved + (K1 - tv) * temp;
            saved = (tv - K2) * temp;
        }
        Nb[k] = saved;
    }

    g_basis[b][t] = make_float4(Nb[0], Nb[1], Nb[2], Nb[3]);
    g_span [b][t] = span;
}

// ---------------------------------------------------------------------------
// Kernel 2: surface evaluation. Block = (u, b); 256 threads over v.
// Stage the 4 control rows selected by uspan plus all v-bases in smem,
// then a fully unrolled 4x4 tensor contraction per output point.
// ---------------------------------------------------------------------------
__global__ void __launch_bounds__(OUTV) eval_kernel(const float* __restrict__ ctrl,
                                                    float* __restrict__ out) {
    const int u = blockIdx.x;
    const int b = blockIdx.y;
    const int t = threadIdx.x;

    __shared__ float4 srow[DEG + 1][NCTRL];  // 4 rows x 64 float4 = 4 KB
    __shared__ float4 sbv[OUTV];             // v basis, 4 KB
    __shared__ int    ssv[OUTV];             // v span-base, 1 KB

    // Load the 4 control rows this u-span touches: su..su+3, each 64 float4.
    const int su = g_span[b][u] - DEG;
    {
        const int row = t >> 6;        // 0..3
        const int col = t & 63;        // 0..63
        const float4* cp = reinterpret_cast<const float4*>(ctrl)
                         + (size_t)b * MCTRL * NCTRL;
        srow[row][col] = cp[(su + row) * NCTRL + col];
    }
    // Load all v bases/spans for this batch.
    sbv[t] = g_basis[b][t];
    ssv[t] = g_span[b][t] - DEG;
    __syncthreads();

    // u basis is uniform across the block (broadcast read).
    const float4 nu4 = g_basis[b][u];
    const float nu[4] = {nu4.x, nu4.y, nu4.z, nu4.w};

    const int v = t;
    const float4 nv4 = sbv[v];
    const float nv[4] = {nv4.x, nv4.y, nv4.z, nv4.w};
    const int sv = ssv[v];

    float ax = 0.f, ay = 0.f, az = 0.f;
    #pragma unroll
    for (int l = 0; l <= DEG; l++) {
        float ix = 0.f, iy = 0.f, iz = 0.f;
        #pragma unroll
        for (int r = 0; r <= DEG; r++) {
            const float4 c = srow[l][sv + r];
            ix = fmaf(nv[r], c.x, ix);
            iy = fmaf(nv[r], c.y, iy);
            iz = fmaf(nv[r], c.z, iz);
        }
        ax = fmaf(nu[l], ix, ax);
        ay = fmaf(nu[l], iy, ay);
        az = fmaf(nu[l], iz, az);
    }

    const size_t o = (((size_t)b * OUTU + u) * OUTV + v) * 3;
    out[o + 0] = ax;
    out[o + 1] = ay;
    out[o + 2] = az;
}

// ---------------------------------------------------------------------------
// Launch: inputs per metadata order: ctrl_pts [16,64,64,4] f32,
//         knot_u [16,68] f32, knot_v [16,68] f32 (unused — reference uses
//         knot_u for both directions).
// ---------------------------------------------------------------------------
extern "C" void kernel_launch(void* const* d_in, const int* in_sizes, int n_in,
                              void* d_out, int out_size) {
    const float* ctrl   = (const float*)d_in[0];
    const float* knot_u = (const float*)d_in[1];
    float* out = (float*)d_out;

    basis_kernel<<<BATCH, OUTU>>>(knot_u);
    eval_kernel<<<dim3(OUTU, BATCH), OUTV>>>(ctrl, out);
}

// round 2
// speedup vs baseline: 2.0466x; 2.0466x over previous
#include <cuda_runtime.h>
#include <cuda_bf16.h>

// Problem constants (fixed by the reference)
#define BATCH 16
#define MCTRL 64
#define NCTRL 64
#define DEG   3
#define LKNOT 68                // M + P + 1
#define NSPAN (LKNOT - 2*DEG)   // 62 candidate spans
#define OUTU  256
#define OUTV  256
#define U_PER 4                 // u samples per eval block

// Scratch (allocation-free rule: __device__ globals).
// Nu == Nv and uspan == vspan because the reference builds V from knot_u and
// the u/v linspaces + degrees are identical. One table serves both directions.
__device__ float4 g_basis[BATCH][OUTU];
__device__ int    g_span [BATCH][OUTU];

// ---------------------------------------------------------------------------
// Kernel 1: normalized knots (parallel scan), span search, Cox-de Boor basis.
// One block per batch, one thread per parameter sample. The cumsum is a
// Hillis-Steele scan in shared memory (log2(68)=7 steps) — no serial
// global-latency chain.
// ---------------------------------------------------------------------------
__global__ void __launch_bounds__(OUTU) basis_kernel(const float* __restrict__ knot_u) {
    const int b = blockIdx.x;
    const int t = threadIdx.x;

    __shared__ float sa[LKNOT];
    __shared__ float K[LKNOT];

    if (t < LKNOT) sa[t] = knot_u[b * LKNOT + t];
    __syncthreads();

    // Inclusive scan (Hillis-Steele).
    #pragma unroll
    for (int off = 1; off < LKNOT; off <<= 1) {
        float v = 0.f;
        if (t < LKNOT) v = sa[t] + ((t >= off) ? sa[t - off] : 0.f);
        __syncthreads();
        if (t < LKNOT) sa[t] = v;
        __syncthreads();
    }
    if (t < LKNOT) {
        const float c0  = sa[0];
        const float den = sa[LKNOT - 1] - c0;
        K[t] = (sa[t] - c0) / den;
    }
    __syncthreads();

    // jnp.linspace(1e-5, 1-1e-5, 256): start + i*step, endpoint exact.
    const float start = 1e-5f;
    const float stop  = 1.0f - 1e-5f;
    const float step  = (stop - start) / (float)(OUTU - 1);
    float tv = start + (float)t * step;
    if (t == OUTU - 1) tv = stop;

    // _find_span: argmin over cand = (d > 1e-8 ? d : 1.0), first-occurrence ties.
    float best = 3.402823466e+38f;
    int   arg  = 0;
    #pragma unroll 1
    for (int s = 0; s < NSPAN; s++) {
        float d    = tv - K[s + DEG];
        float cand = (d > 1e-8f) ? d : 1.0f;
        if (cand < best) { best = cand; arg = s; }
    }
    const int span = arg + DEG;

    // Cox-de Boor recursion, mirroring the reference arithmetic exactly
    // (including the (K1 - t) + (t - K2) denominator form).
    float Nb[DEG + 1];
    Nb[0] = 1.f;
    #pragma unroll
    for (int k = 1; k <= DEG; k++) {
        float saved = 0.f;
        #pragma unroll
        for (int r = 0; r < k; r++) {
            const float K1 = K[span + r + 1];
            const float K2 = K[span + 1 - k + r];
            const float denom = (K1 - tv) + (tv - K2);
            const float temp  = Nb[r] / denom;
            Nb[r] = saved + (K1 - tv) * temp;
            saved = (tv - K2) * temp;
        }
        Nb[k] = saved;
    }

    g_basis[b][t] = make_float4(Nb[0], Nb[1], Nb[2], Nb[3]);
    g_span [b][t] = span;
}

// ---------------------------------------------------------------------------
// Kernel 2: separable surface evaluation.
// Block = (u-group of 4, b); 256 threads.
// Stage A: fold nu into per-u temp rows tmp[u'][n] = sum_l nu[l]*ctrl[su+l][n]
//          (thread t -> u'=t>>6, n=t&63; 4 coalesced LDG.128 each).
// Stage B: each thread evaluates one v for all 4 u's: 4 LDS.128 + 12 FMA per
//          output point (was 16 LDS.128 + 24 FMA).
// ---------------------------------------------------------------------------
__global__ void __launch_bounds__(OUTV) eval_kernel(const float* __restrict__ ctrl,
                                                    float* __restrict__ out) {
    const int u0 = blockIdx.x * U_PER;
    const int b  = blockIdx.y;
    const int t  = threadIdx.x;

    __shared__ float4 sbv[OUTV];            // v basis, 4 KB
    __shared__ int    ssv[OUTV];            // v span-base, 1 KB
    __shared__ float4 stmp[U_PER][NCTRL];   // u-folded rows, 4 KB

    // Stage v basis/spans for this batch (one LDG.128 + LDG.32 per thread).
    sbv[t] = g_basis[b][t];
    ssv[t] = g_span[b][t] - DEG;

    // Stage A: u-fold. thread t handles (u' = t>>6, n = t&63).
    {
        const int up = t >> 6;
        const int n  = t & 63;
        const int u  = u0 + up;
        const int su = g_span[b][u] - DEG;
        const float4 nu = g_basis[b][u];
        const float4* cp = reinterpret_cast<const float4*>(ctrl)
                         + (size_t)b * MCTRL * NCTRL + n;

        const float4 c0 = cp[(su + 0) * NCTRL];
        const float4 c1 = cp[(su + 1) * NCTRL];
        const float4 c2 = cp[(su + 2) * NCTRL];
        const float4 c3 = cp[(su + 3) * NCTRL];

        float4 r;
        r.x = fmaf(nu.x, c0.x, fmaf(nu.y, c1.x, fmaf(nu.z, c2.x, nu.w * c3.x)));
        r.y = fmaf(nu.x, c0.y, fmaf(nu.y, c1.y, fmaf(nu.z, c2.y, nu.w * c3.y)));
        r.z = fmaf(nu.x, c0.z, fmaf(nu.y, c1.z, fmaf(nu.z, c2.z, nu.w * c3.z)));
        r.w = 0.f;
        stmp[up][n] = r;
    }
    __syncthreads();

    // Stage B: per-v contraction over the folded rows.
    const int v = t;
    const float4 nv = sbv[v];
    const int   sv = ssv[v];

    float* op = out + (((size_t)b * OUTU + u0) * OUTV + v) * 3;

    #pragma unroll
    for (int up = 0; up < U_PER; up++) {
        const float4 c0 = stmp[up][sv + 0];
        const float4 c1 = stmp[up][sv + 1];
        const float4 c2 = stmp[up][sv + 2];
        const float4 c3 = stmp[up][sv + 3];

        const float ax = fmaf(nv.x, c0.x, fmaf(nv.y, c1.x, fmaf(nv.z, c2.x, nv.w * c3.x)));
        const float ay = fmaf(nv.x, c0.y, fmaf(nv.y, c1.y, fmaf(nv.z, c2.y, nv.w * c3.y)));
        const float az = fmaf(nv.x, c0.z, fmaf(nv.y, c1.z, fmaf(nv.z, c2.z, nv.w * c3.z)));

        float* o = op + (size_t)up * OUTV * 3;
        o[0] = ax;
        o[1] = ay;
        o[2] = az;
    }
}

// ---------------------------------------------------------------------------
// Launch. Inputs per metadata order: ctrl_pts [16,64,64,4] f32,
// knot_u [16,68] f32, knot_v [16,68] f32 (unused — the reference builds both
// directions from knot_u).
// ---------------------------------------------------------------------------
extern "C" void kernel_launch(void* const* d_in, const int* in_sizes, int n_in,
                              void* d_out, int out_size) {
    const float* ctrl   = (const float*)d_in[0];
    const float* knot_u = (const float*)d_in[1];
    float* out = (float*)d_out;

    basis_kernel<<<BATCH, OUTU>>>(knot_u);
    eval_kernel<<<dim3(OUTU / U_PER, BATCH), OUTV>>>(ctrl, out);
}

// round 3
// speedup vs baseline: 2.8836x; 1.4090x over previous
#include <cuda_runtime.h>
#include <cuda_bf16.h>

// Problem constants (fixed by the reference)
#define BATCH 16
#define MCTRL 64
#define NCTRL 64
#define DEG   3
#define LKNOT 68                // M + P + 1
#define NSPAN (LKNOT - 2*DEG)   // 62 candidate spans
#define OUTU  256
#define OUTV  256
#define U_PER 8                 // u samples per block

// Fully fused kernel.
// Grid: (OUTU/U_PER, BATCH) = (32, 16) blocks x 256 threads.
//
// Per block:
//   1. Load this batch's 68 knots, inclusive-scan them with a 3-warp shfl
//      scan (2 barriers), normalize -> K[0..67] in smem.
//      (Nu == Nv and uspan == vspan: the reference builds V from knot_u and
//       u/v linspaces + degrees are identical -> one table serves both axes.)
//   2. Every thread computes the basis for sample t (span via branchless
//      prefix count, Cox-de Boor deg 3) -> sbv/ssv in smem.
//   3. Stage A: fold the u basis into per-u temp rows
//      stmp[up][n] = sum_l nu[l] * ctrl[su+l][n]  (coalesced LDG.128).
//   4. Stage B: per-thread v contraction: 4 LDS.128 + 12 FMA per point.
__global__ void __launch_bounds__(256) surf_kernel(const float* __restrict__ ctrl,
                                                   const float* __restrict__ knot_u,
                                                   float* __restrict__ out) {
    const int u0 = blockIdx.x * U_PER;
    const int b  = blockIdx.y;
    const int t  = threadIdx.x;

    __shared__ float  sc[LKNOT];          // raw cumsum workspace
    __shared__ float  stot[3];            // per-warp scan totals
    __shared__ float  K[LKNOT];           // normalized knots
    __shared__ float4 sbv[OUTV];          // basis per sample (4 KB)
    __shared__ int    ssv[OUTV];          // span-base per sample (1 KB)
    __shared__ float4 stmp[U_PER][NCTRL]; // u-folded rows (8 KB)

    // ---- 1. knots + scan + normalize -------------------------------------
    if (t < LKNOT) sc[t] = knot_u[b * LKNOT + t];
    __syncthreads();

    if (t < 96) {  // warps 0..2 cover 68 elements
        const int lane = t & 31;
        float v = (t < LKNOT) ? sc[t] : 0.f;
        #pragma unroll
        for (int off = 1; off < 32; off <<= 1) {
            const float n = __shfl_up_sync(0xffffffffu, v, off);
            if (lane >= off) v += n;
        }
        if (t < LKNOT) sc[t] = v;
        if (lane == 31) stot[t >> 5] = v;
    }
    __syncthreads();

    if (t < LKNOT) {
        float v = sc[t];
        if (t >= 32) v += stot[0];
        if (t >= 64) v += stot[1];
        const float c0   = sc[0];
        const float clast = sc[LKNOT - 1] + stot[0] + stot[1];
        K[t] = (v - c0) / (clast - c0);
    }
    __syncthreads();

    // ---- 2. per-sample basis ---------------------------------------------
    {
        // jnp.linspace(1e-5, 1-1e-5, 256): start + i*step, endpoint exact.
        const float start = 1e-5f;
        const float stop  = 1.0f - 1e-5f;
        const float step  = (stop - start) / (float)(OUTU - 1);
        float tv = start + (float)t * step;
        if (t == OUTU - 1) tv = stop;

        // _find_span: argmin over (d > 1e-8 ? d : 1.0). d = tv - K[s+DEG] is
        // monotone non-increasing in s, so the minimizer (first occurrence)
        // equals (#valid entries) - 1. Same fp predicate as the reference.
        int cnt = 0;
        #pragma unroll
        for (int s = 0; s < NSPAN; s++)
            cnt += ((tv - K[s + DEG]) > 1e-8f) ? 1 : 0;
        const int span = DEG + cnt - 1;

        // Cox-de Boor (mirrors the reference arithmetic, including the
        // (K1 - t) + (t - K2) denominator form).
        float Nb[DEG + 1];
        Nb[0] = 1.f;
        #pragma unroll
        for (int k = 1; k <= DEG; k++) {
            float saved = 0.f;
            #pragma unroll
            for (int r = 0; r < k; r++) {
                const float K1 = K[span + r + 1];
                const float K2 = K[span + 1 - k + r];
                const float denom = (K1 - tv) + (tv - K2);
                const float temp  = Nb[r] / denom;
                Nb[r] = saved + (K1 - tv) * temp;
                saved = (tv - K2) * temp;
            }
            Nb[k] = saved;
        }

        sbv[t] = make_float4(Nb[0], Nb[1], Nb[2], Nb[3]);
        ssv[t] = span - DEG;
    }
    __syncthreads();

    // ---- 3. Stage A: u-fold ----------------------------------------------
    #pragma unroll
    for (int task = t; task < U_PER * NCTRL; task += 256) {
        const int up = task >> 6;
        const int n  = task & 63;
        const int u  = u0 + up;
        const int su = ssv[u];
        const float4 nu = sbv[u];
        const float4* cp = reinterpret_cast<const float4*>(ctrl)
                         + (size_t)b * MCTRL * NCTRL + n;

        const float4 c0 = cp[(su + 0) * NCTRL];
        const float4 c1 = cp[(su + 1) * NCTRL];
        const float4 c2 = cp[(su + 2) * NCTRL];
        const float4 c3 = cp[(su + 3) * NCTRL];

        float4 r;
        r.x = fmaf(nu.x, c0.x, fmaf(nu.y, c1.x, fmaf(nu.z, c2.x, nu.w * c3.x)));
        r.y = fmaf(nu.x, c0.y, fmaf(nu.y, c1.y, fmaf(nu.z, c2.y, nu.w * c3.y)));
        r.z = fmaf(nu.x, c0.z, fmaf(nu.y, c1.z, fmaf(nu.z, c2.z, nu.w * c3.z)));
        r.w = 0.f;
        stmp[up][n] = r;
    }
    __syncthreads();

    // ---- 4. Stage B: per-v contraction ------------------------------------
    const int v = t;
    const float4 nv = sbv[v];
    const int   sv = ssv[v];

    float* op = out + (((size_t)b * OUTU + u0) * OUTV + v) * 3;

    #pragma unroll
    for (int up = 0; up < U_PER; up++) {
        const float4 c0 = stmp[up][sv + 0];
        const float4 c1 = stmp[up][sv + 1];
        const float4 c2 = stmp[up][sv + 2];
        const float4 c3 = stmp[up][sv + 3];

        const float ax = fmaf(nv.x, c0.x, fmaf(nv.y, c1.x, fmaf(nv.z, c2.x, nv.w * c3.x)));
        const float ay = fmaf(nv.x, c0.y, fmaf(nv.y, c1.y, fmaf(nv.z, c2.y, nv.w * c3.y)));
        const float az = fmaf(nv.x, c0.z, fmaf(nv.y, c1.z, fmaf(nv.z, c2.z, nv.w * c3.z)));

        float* o = op + (size_t)up * OUTV * 3;
        o[0] = ax;
        o[1] = ay;
        o[2] = az;
    }
}

// ---------------------------------------------------------------------------
// Launch. Inputs per metadata order: ctrl_pts [16,64,64,4] f32,
// knot_u [16,68] f32, knot_v [16,68] f32 (unused — the reference builds both
// directions from knot_u).
// ---------------------------------------------------------------------------
extern "C" void kernel_launch(void* const* d_in, const int* in_sizes, int n_in,
                              void* d_out, int out_size) {
    const float* ctrl   = (const float*)d_in[0];
    const float* knot_u = (const float*)d_in[1];
    float* out = (float*)d_out;

    surf_kernel<<<dim3(OUTU / U_PER, BATCH), 256>>>(ctrl, knot_u, out);
}